// round 8
// baseline (speedup 1.0000x reference)
#include <cuda_runtime.h>
#include <cuda_bf16.h>
#include <math.h>

// SurfNetwork v7: v6 + loop-invariant W1/b1 fragments hoisted to registers
// (removes ~80 LDS per warp-iter and the LDS links in layer-1's mma chain).
// Prefetch folds gathers to packed bf16 geo + sigma product to pay registers.
// 2 blocks/SM.

#define BN   128
#define LVL  6
#define DIRD 16
#define GEO  18

#define SW0G 20
#define SW1  36
#define SW2  36
#define SAG  20
#define SCB  9

typedef unsigned int u32;

#define O_W0GT 0        // 64*20
#define O_W1T  1280     // 64*36
#define O_W2T  3584     // 8*36
#define O_W0D  3872     // 16*64 fp32
#define O_B0   4896
#define O_B1   4960
#define O_B2   5024
#define O_BASE 5032
#define O_SIG  5096
#define O_MAX  5224
#define O_COL  5228
#define O_ACTG 5240     // 128*20
#define O_COLB 7800     // 128*9 fp32
#define SMEM_WORDS 8952
#define SMEM_BYTES (SMEM_WORDS * 4)   // 35808

__device__ __forceinline__ u32 pkbf(float lo, float hi) {
    u32 r; asm("cvt.rn.bf16x2.f32 %0, %1, %2;" : "=r"(r) : "f"(hi), "f"(lo));
    return r;
}
__device__ __forceinline__ u32 pkrelu(float lo, float hi) {
    return pkbf(fmaxf(lo, 0.0f), fmaxf(hi, 0.0f));
}
__device__ __forceinline__ void mma16(float* c, const u32* a, u32 b0, u32 b1) {
    asm volatile(
        "mma.sync.aligned.m16n8k16.row.col.f32.bf16.bf16.f32 "
        "{%0,%1,%2,%3},{%4,%5,%6,%7},{%8,%9},{%0,%1,%2,%3};"
        : "+f"(c[0]), "+f"(c[1]), "+f"(c[2]), "+f"(c[3])
        : "r"(a[0]), "r"(a[1]), "r"(a[2]), "r"(a[3]), "r"(b0), "r"(b1));
}
__device__ __forceinline__ int agix(int row, int j) {
    return row * SAG + (j ^ ((row >> 3) & 3));
}

__global__ void __launch_bounds__(128, 2)
surf_hoist(const int* __restrict__ x,
           const float* __restrict__ dvec,
           const float4* __restrict__ gw,
           const float* __restrict__ W0, const float* __restrict__ b0,
           const float* __restrict__ W1, const float* __restrict__ b1,
           const float* __restrict__ W2, const float* __restrict__ b2,
           float* __restrict__ outSigma, float* __restrict__ outColor,
           int B)
{
    extern __shared__ float sm[];
    u32* smu = (u32*)sm;
    const int tid  = threadIdx.x;
    const int lane = tid & 31;
    const int warp = tid >> 5;
    const int grp  = lane >> 2;
    const int tig  = lane & 3;

    // ---------- stage weights (transposed, bf16x2) ----------
    for (int i = tid; i < 64 * SW0G; i += 128) {
        int n = i / SW0G, kk = i - n * SW0G;
        u32 v = 0;
        if (kk < 16) {
            int g0 = 2 * kk, g1 = 2 * kk + 1;
            float lo = (g0 < GEO) ? W0[(DIRD + g0) * 64 + n] : 0.0f;
            float hi = (g1 < GEO) ? W0[(DIRD + g1) * 64 + n] : 0.0f;
            v = pkbf(lo, hi);
        }
        smu[O_W0GT + i] = v;
    }
    for (int i = tid; i < 64 * SW1; i += 128) {
        int n = i / SW1, kk = i - n * SW1;
        u32 v = 0;
        if (kk < 32) v = pkbf(W1[(2 * kk) * 64 + n], W1[(2 * kk + 1) * 64 + n]);
        smu[O_W1T + i] = v;
    }
    for (int i = tid; i < 8 * SW2; i += 128) {
        int n = i / SW2, kk = i - n * SW2;
        u32 v = 0;
        if (kk < 32 && n < 3) v = pkbf(W2[(2 * kk) * 3 + n], W2[(2 * kk + 1) * 3 + n]);
        smu[O_W2T + i] = v;
    }
    for (int i = tid; i < DIRD * 64; i += 128) sm[O_W0D + i] = W0[i];
    if (tid < 64) { sm[O_B0 + tid] = b0[tid]; sm[O_B1 + tid] = b1[tid]; }
    if (tid < 8)  sm[O_B2 + tid] = (tid < 3) ? b2[tid] : 0.0f;
    for (int j = 9; j < 16; j++) smu[O_ACTG + agix(tid, j)] = 0;
    __syncthreads();

    // ---------- hoist loop-invariant W1 / b1 fragments to registers ----------
    u32 W1h[4][4][4];
    float b1h[4][4];
    #pragma unroll
    for (int kg = 0; kg < 4; kg++) {
        #pragma unroll
        for (int k = 0; k < 4; k++) {
            W1h[kg][k][0] = smu[O_W1T + ((2 * kg) * 8 + grp) * SW1 + k * 8 + tig];
            W1h[kg][k][1] = smu[O_W1T + ((2 * kg) * 8 + grp) * SW1 + k * 8 + 4 + tig];
            W1h[kg][k][2] = smu[O_W1T + ((2 * kg + 1) * 8 + grp) * SW1 + k * 8 + tig];
            W1h[kg][k][3] = smu[O_W1T + ((2 * kg + 1) * 8 + grp) * SW1 + k * 8 + 4 + tig];
        }
        b1h[kg][0] = sm[O_B1 + (2 * kg) * 8 + 2 * tig];
        b1h[kg][1] = sm[O_B1 + (2 * kg) * 8 + 2 * tig + 1];
        b1h[kg][2] = sm[O_B1 + (2 * kg + 1) * 8 + 2 * tig];
        b1h[kg][3] = sm[O_B1 + (2 * kg + 1) * 8 + 2 * tig + 1];
    }

    const int gstride = gridDim.x;
    int row = blockIdx.x;

    // ---------- prologue prefetch: packed geo + sigma product ----------
    u32   gpk[9];
    float sgpre;
    float dpre[DIRD];
    {
        const int2* xp2 = (const int2*)(x + ((size_t)row * BN + tid) * LVL);
        int2 xv0 = __ldg(xp2), xv1 = __ldg(xp2 + 1), xv2 = __ldg(xp2 + 2);
        if (tid < 64) {
            const float* dd = dvec + (size_t)row * DIRD;
            #pragma unroll
            for (int i = 0; i < DIRD; i++) dpre[i] = __ldg(dd + i);
        }
        float4 f0 = __ldg(gw + xv0.x), f1 = __ldg(gw + xv0.y);
        float4 f2 = __ldg(gw + xv1.x), f3 = __ldg(gw + xv1.y);
        float4 f4v = __ldg(gw + xv2.x), f5 = __ldg(gw + xv2.y);
        sgpre = fminf(fmaxf(f0.x, 0.f), 1.f) * fminf(fmaxf(f1.x, 0.f), 1.f)
              * fminf(fmaxf(f2.x, 0.f), 1.f) * fminf(fmaxf(f3.x, 0.f), 1.f)
              * fminf(fmaxf(f4v.x, 0.f), 1.f) * fminf(fmaxf(f5.x, 0.f), 1.f);
        gpk[0] = pkbf(f0.y, f0.z); gpk[1] = pkbf(f0.w, f1.y); gpk[2] = pkbf(f1.z, f1.w);
        gpk[3] = pkbf(f2.y, f2.z); gpk[4] = pkbf(f2.w, f3.y); gpk[5] = pkbf(f3.z, f3.w);
        gpk[6] = pkbf(f4v.y, f4v.z); gpk[7] = pkbf(f4v.w, f5.y); gpk[8] = pkbf(f5.z, f5.w);
    }

    while (row < B) {
        const int nrow = row + gstride;
        const bool pn = nrow < B;

        // ============ phase 1: consume prefetched ============
        if (tid < 64) {
            float acc = sm[O_B0 + tid];
            #pragma unroll
            for (int i = 0; i < DIRD; i++)
                acc = fmaf(dpre[i], sm[O_W0D + i * 64 + tid], acc);
            sm[O_BASE + tid] = acc;
        }
        float sg = sgpre + 1e-4f;
        sm[O_SIG + tid] = sg;
        #pragma unroll
        for (int j = 0; j < 9; j++) smu[O_ACTG + agix(tid, j)] = gpk[j];

        float m = sg;
        #pragma unroll
        for (int o = 16; o; o >>= 1) m = fmaxf(m, __shfl_xor_sync(0xffffffffu, m, o));
        if (lane == 0) sm[O_MAX + warp] = m;
        __syncthreads();   // (A)
        m = fmaxf(fmaxf(sm[O_MAX + 0], sm[O_MAX + 1]), fmaxf(sm[O_MAX + 2], sm[O_MAX + 3]));

        float sigma = sg / m;
        outSigma[(size_t)row * BN + tid] = sigma;
        float tb = tid ? 1.0f - sm[O_SIG + tid - 1] / m : 1.0f;
        float cw = tb * sigma;

        // ---- prefetch stage 1: next row's x + d ----
        int2 xv0, xv1, xv2;
        if (pn) {
            const int2* xp2 = (const int2*)(x + ((size_t)nrow * BN + tid) * LVL);
            xv0 = __ldg(xp2); xv1 = __ldg(xp2 + 1); xv2 = __ldg(xp2 + 2);
            if (tid < 64) {
                const float* dd = dvec + (size_t)nrow * DIRD;
                #pragma unroll
                for (int i = 0; i < DIRD; i++) dpre[i] = __ldg(dd + i);
            }
        }

        const int r0 = warp * 32 + grp;

        // ============ layer 0 -> A1 registers ============
        u32 A1[2][4][4];
        {
            u32 Ag[2][2][4];
            const u32* AG = smu + O_ACTG;
            #pragma unroll
            for (int mt = 0; mt < 2; mt++) {
                int rA = r0 + mt * 16, rB = rA + 8;
                #pragma unroll
                for (int k = 0; k < 2; k++) {
                    Ag[mt][k][0] = AG[agix(rA, k * 8 + tig)];
                    Ag[mt][k][1] = AG[agix(rB, k * 8 + tig)];
                    Ag[mt][k][2] = AG[agix(rA, k * 8 + 4 + tig)];
                    Ag[mt][k][3] = AG[agix(rB, k * 8 + 4 + tig)];
                }
            }
            const u32* WT = smu + O_W0GT;
            #pragma unroll
            for (int kg = 0; kg < 4; kg++) {
                float Ca[2][4], Cb[2][4];
                #pragma unroll
                for (int mt = 0; mt < 2; mt++) {
                    float v0 = sm[O_BASE + (2 * kg) * 8 + 2 * tig];
                    float v1 = sm[O_BASE + (2 * kg) * 8 + 2 * tig + 1];
                    Ca[mt][0] = v0; Ca[mt][1] = v1; Ca[mt][2] = v0; Ca[mt][3] = v1;
                    v0 = sm[O_BASE + (2 * kg + 1) * 8 + 2 * tig];
                    v1 = sm[O_BASE + (2 * kg + 1) * 8 + 2 * tig + 1];
                    Cb[mt][0] = v0; Cb[mt][1] = v1; Cb[mt][2] = v0; Cb[mt][3] = v1;
                }
                #pragma unroll
                for (int k = 0; k < 2; k++) {
                    u32 ba0 = WT[((2 * kg) * 8 + grp) * SW0G + k * 8 + tig];
                    u32 ba1 = WT[((2 * kg) * 8 + grp) * SW0G + k * 8 + 4 + tig];
                    u32 bb0 = WT[((2 * kg + 1) * 8 + grp) * SW0G + k * 8 + tig];
                    u32 bb1 = WT[((2 * kg + 1) * 8 + grp) * SW0G + k * 8 + 4 + tig];
                    #pragma unroll
                    for (int mt = 0; mt < 2; mt++) {
                        mma16(Ca[mt], Ag[mt][k], ba0, ba1);
                        mma16(Cb[mt], Ag[mt][k], bb0, bb1);
                    }
                }
                #pragma unroll
                for (int mt = 0; mt < 2; mt++) {
                    A1[mt][kg][0] = pkrelu(Ca[mt][0], Ca[mt][1]);
                    A1[mt][kg][1] = pkrelu(Ca[mt][2], Ca[mt][3]);
                    A1[mt][kg][2] = pkrelu(Cb[mt][0], Cb[mt][1]);
                    A1[mt][kg][3] = pkrelu(Cb[mt][2], Cb[mt][3]);
                }
            }
        }

        // ---- prefetch stage 2: dependent gathers -> packed form ----
        if (pn) {
            float4 f0 = __ldg(gw + xv0.x), f1 = __ldg(gw + xv0.y);
            float4 f2 = __ldg(gw + xv1.x), f3 = __ldg(gw + xv1.y);
            float4 f4v = __ldg(gw + xv2.x), f5 = __ldg(gw + xv2.y);
            sgpre = fminf(fmaxf(f0.x, 0.f), 1.f) * fminf(fmaxf(f1.x, 0.f), 1.f)
                  * fminf(fmaxf(f2.x, 0.f), 1.f) * fminf(fmaxf(f3.x, 0.f), 1.f)
                  * fminf(fmaxf(f4v.x, 0.f), 1.f) * fminf(fmaxf(f5.x, 0.f), 1.f);
            gpk[0] = pkbf(f0.y, f0.z); gpk[1] = pkbf(f0.w, f1.y); gpk[2] = pkbf(f1.z, f1.w);
            gpk[3] = pkbf(f2.y, f2.z); gpk[4] = pkbf(f2.w, f3.y); gpk[5] = pkbf(f3.z, f3.w);
            gpk[6] = pkbf(f4v.y, f4v.z); gpk[7] = pkbf(f4v.w, f5.y); gpk[8] = pkbf(f5.z, f5.w);
        }

        // ============ layer 1 (register weights) -> A2 ============
        u32 A2[2][4][4];
        #pragma unroll
        for (int kg = 0; kg < 4; kg++) {
            float Ca[2][4], Cb[2][4];
            #pragma unroll
            for (int mt = 0; mt < 2; mt++) {
                Ca[mt][0] = b1h[kg][0]; Ca[mt][1] = b1h[kg][1];
                Ca[mt][2] = b1h[kg][0]; Ca[mt][3] = b1h[kg][1];
                Cb[mt][0] = b1h[kg][2]; Cb[mt][1] = b1h[kg][3];
                Cb[mt][2] = b1h[kg][2]; Cb[mt][3] = b1h[kg][3];
            }
            #pragma unroll
            for (int k = 0; k < 4; k++) {
                #pragma unroll
                for (int mt = 0; mt < 2; mt++) {
                    mma16(Ca[mt], A1[mt][k], W1h[kg][k][0], W1h[kg][k][1]);
                    mma16(Cb[mt], A1[mt][k], W1h[kg][k][2], W1h[kg][k][3]);
                }
            }
            #pragma unroll
            for (int mt = 0; mt < 2; mt++) {
                A2[mt][kg][0] = pkrelu(Ca[mt][0], Ca[mt][1]);
                A2[mt][kg][1] = pkrelu(Ca[mt][2], Ca[mt][3]);
                A2[mt][kg][2] = pkrelu(Cb[mt][0], Cb[mt][1]);
                A2[mt][kg][3] = pkrelu(Cb[mt][2], Cb[mt][3]);
            }
        }

        // ============ layer 2 -> logits ============
        {
            const u32* WT = smu + O_W2T;
            float bv0 = sm[O_B2 + 2 * tig];
            float bv1 = sm[O_B2 + 2 * tig + 1];
            float C0[4] = {bv0, bv1, bv0, bv1};
            float C1[4] = {bv0, bv1, bv0, bv1};
            #pragma unroll
            for (int k = 0; k < 4; k++) {
                u32 bb0 = WT[grp * SW2 + k * 8 + tig];
                u32 bb1 = WT[grp * SW2 + k * 8 + 4 + tig];
                mma16(C0, A2[0][k], bb0, bb1);
                mma16(C1, A2[1][k], bb0, bb1);
            }
            const int r1 = r0 + 16;
            if (2 * tig < 3) {
                sm[O_COLB + r0 * SCB + 2 * tig]        = C0[0];
                sm[O_COLB + (r0 + 8) * SCB + 2 * tig]  = C0[2];
                sm[O_COLB + r1 * SCB + 2 * tig]        = C1[0];
                sm[O_COLB + (r1 + 8) * SCB + 2 * tig]  = C1[2];
            }
            if (2 * tig + 1 < 3) {
                sm[O_COLB + r0 * SCB + 2 * tig + 1]       = C0[1];
                sm[O_COLB + (r0 + 8) * SCB + 2 * tig + 1] = C0[3];
                sm[O_COLB + r1 * SCB + 2 * tig + 1]       = C1[1];
                sm[O_COLB + (r1 + 8) * SCB + 2 * tig + 1] = C1[3];
            }
        }
        __syncwarp();

        // ============ phase 3 ============
        float l0 = sm[O_COLB + tid * SCB + 0];
        float l1 = sm[O_COLB + tid * SCB + 1];
        float l2 = sm[O_COLB + tid * SCB + 2];
        float c0 = 1.0f / (1.0f + expf(-l0));
        float c1 = 1.0f / (1.0f + expf(-l1));
        float c2 = 1.0f / (1.0f + expf(-l2));
        float rr = cw * c0, gg = cw * c1, bb = cw * c2;
        #pragma unroll
        for (int o = 16; o; o >>= 1) {
            rr += __shfl_xor_sync(0xffffffffu, rr, o);
            gg += __shfl_xor_sync(0xffffffffu, gg, o);
            bb += __shfl_xor_sync(0xffffffffu, bb, o);
        }
        if (lane == 0) {
            sm[O_COL + warp * 3 + 0] = rr;
            sm[O_COL + warp * 3 + 1] = gg;
            sm[O_COL + warp * 3 + 2] = bb;
        }
        __syncthreads();   // (C)
        if (tid < 3) {
            outColor[(size_t)row * 3 + tid] =
                sm[O_COL + tid] + sm[O_COL + 3 + tid] +
                sm[O_COL + 6 + tid] + sm[O_COL + 9 + tid];
        }
        row = nrow;
    }
}

extern "C" void kernel_launch(void* const* d_in, const int* in_sizes, int n_in,
                              void* d_out, int out_size)
{
    const int*    x  = (const int*)d_in[0];
    const float*  dv = (const float*)d_in[1];
    const float4* gw = (const float4*)d_in[2];
    const float*  W0 = (const float*)d_in[3];
    const float*  b0 = (const float*)d_in[4];
    const float*  W1 = (const float*)d_in[5];
    const float*  b1 = (const float*)d_in[6];
    const float*  W2 = (const float*)d_in[7];
    const float*  b2 = (const float*)d_in[8];

    const int B = in_sizes[0] / (BN * LVL);   // 16384
    float* outSigma = (float*)d_out;
    float* outColor = (float*)d_out + (size_t)B * BN;

    cudaFuncSetAttribute(surf_hoist,
                         cudaFuncAttributeMaxDynamicSharedMemorySize, SMEM_BYTES);

    int grid = B < 296 ? B : 296;   // 2 blocks/SM persistent
    surf_hoist<<<grid, 128, SMEM_BYTES>>>(x, dv, gw, W0, b0, W1, b1, W2, b2,
                                          outSigma, outColor, B);
}

// round 9
// speedup vs baseline: 1.2408x; 1.2408x over previous
#include <cuda_runtime.h>
#include <cuda_bf16.h>
#include <math.h>

// SurfNetwork v8: v6 layout + single __syncthreads per row.
//  - row max published pre-MLP (warp shuffle + STS), consumed post-MLP barrier
//  - base computed per-warp (shuffle-broadcast), warp-private smem
//  - color output deferred one iteration via parity-buffered partials
//  - packed prefetch (bf16x2 geo + sigma product) keeps regs ~v6 level
// 3 blocks/SM persistent.

#define BN   128
#define LVL  6
#define DIRD 16
#define GEO  18

#define SW0G 20
#define SW1  36
#define SW2  36
#define SAG  20
#define SCB  9

typedef unsigned int u32;

#define O_W0GT 0        // 64*20
#define O_W1T  1280     // 64*36
#define O_W2T  3584     // 8*36
#define O_W0D  3872     // 16*64 fp32
#define O_B0   4896     // 64
#define O_B1   4960     // 64
#define O_B2   5024     // 8
#define O_BASEW 5032    // 4 warps * 64 (warp-private base)
#define O_SIGP 5288     // 2 * 128 (parity)
#define O_MAXP 5544     // 2 * 4
#define O_COLP 5552     // 2 * 12
#define O_ACTG 5576     // 128*20
#define O_COLB 8136     // 128*9 fp32
#define SMEM_WORDS 9288
#define SMEM_BYTES (SMEM_WORDS * 4)   // 37152

__device__ __forceinline__ u32 pkbf(float lo, float hi) {
    u32 r; asm("cvt.rn.bf16x2.f32 %0, %1, %2;" : "=r"(r) : "f"(hi), "f"(lo));
    return r;
}
__device__ __forceinline__ u32 pkrelu(float lo, float hi) {
    return pkbf(fmaxf(lo, 0.0f), fmaxf(hi, 0.0f));
}
__device__ __forceinline__ void mma16(float* c, const u32* a, u32 b0, u32 b1) {
    asm volatile(
        "mma.sync.aligned.m16n8k16.row.col.f32.bf16.bf16.f32 "
        "{%0,%1,%2,%3},{%4,%5,%6,%7},{%8,%9},{%0,%1,%2,%3};"
        : "+f"(c[0]), "+f"(c[1]), "+f"(c[2]), "+f"(c[3])
        : "r"(a[0]), "r"(a[1]), "r"(a[2]), "r"(a[3]), "r"(b0), "r"(b1));
}
__device__ __forceinline__ int agix(int row, int j) {
    return row * SAG + (j ^ ((row >> 3) & 3));
}

__global__ void __launch_bounds__(128, 3)
surf_onesync(const int* __restrict__ x,
             const float* __restrict__ dvec,
             const float4* __restrict__ gw,
             const float* __restrict__ W0, const float* __restrict__ b0,
             const float* __restrict__ W1, const float* __restrict__ b1,
             const float* __restrict__ W2, const float* __restrict__ b2,
             float* __restrict__ outSigma, float* __restrict__ outColor,
             int B)
{
    extern __shared__ float sm[];
    u32* smu = (u32*)sm;
    const int tid  = threadIdx.x;
    const int lane = tid & 31;
    const int warp = tid >> 5;
    const int grp  = lane >> 2;
    const int tig  = lane & 3;

    // ---------- stage weights (transposed, bf16x2) ----------
    for (int i = tid; i < 64 * SW0G; i += 128) {
        int n = i / SW0G, kk = i - n * SW0G;
        u32 v = 0;
        if (kk < 16) {
            int g0 = 2 * kk, g1 = 2 * kk + 1;
            float lo = (g0 < GEO) ? W0[(DIRD + g0) * 64 + n] : 0.0f;
            float hi = (g1 < GEO) ? W0[(DIRD + g1) * 64 + n] : 0.0f;
            v = pkbf(lo, hi);
        }
        smu[O_W0GT + i] = v;
    }
    for (int i = tid; i < 64 * SW1; i += 128) {
        int n = i / SW1, kk = i - n * SW1;
        u32 v = 0;
        if (kk < 32) v = pkbf(W1[(2 * kk) * 64 + n], W1[(2 * kk + 1) * 64 + n]);
        smu[O_W1T + i] = v;
    }
    for (int i = tid; i < 8 * SW2; i += 128) {
        int n = i / SW2, kk = i - n * SW2;
        u32 v = 0;
        if (kk < 32 && n < 3) v = pkbf(W2[(2 * kk) * 3 + n], W2[(2 * kk + 1) * 3 + n]);
        smu[O_W2T + i] = v;
    }
    for (int i = tid; i < DIRD * 64; i += 128) sm[O_W0D + i] = W0[i];
    if (tid < 64) { sm[O_B0 + tid] = b0[tid]; sm[O_B1 + tid] = b1[tid]; }
    if (tid < 8)  sm[O_B2 + tid] = (tid < 3) ? b2[tid] : 0.0f;
    for (int j = 9; j < 16; j++) smu[O_ACTG + agix(tid, j)] = 0;
    __syncthreads();

    const int gstride = gridDim.x;
    int row = blockIdx.x;
    int prevRow = -1;
    int par = 0;

    // ---------- prologue prefetch ----------
    u32   gpk[9];
    float sgpre, dpre;
    {
        const int2* xp2 = (const int2*)(x + ((size_t)row * BN + tid) * LVL);
        int2 xv0 = __ldg(xp2), xv1 = __ldg(xp2 + 1), xv2 = __ldg(xp2 + 2);
        dpre = (lane < DIRD) ? __ldg(dvec + (size_t)row * DIRD + lane) : 0.0f;
        float4 f0 = __ldg(gw + xv0.x), f1 = __ldg(gw + xv0.y);
        float4 f2 = __ldg(gw + xv1.x), f3 = __ldg(gw + xv1.y);
        float4 f4v = __ldg(gw + xv2.x), f5 = __ldg(gw + xv2.y);
        sgpre = fminf(fmaxf(f0.x, 0.f), 1.f) * fminf(fmaxf(f1.x, 0.f), 1.f)
              * fminf(fmaxf(f2.x, 0.f), 1.f) * fminf(fmaxf(f3.x, 0.f), 1.f)
              * fminf(fmaxf(f4v.x, 0.f), 1.f) * fminf(fmaxf(f5.x, 0.f), 1.f);
        gpk[0] = pkbf(f0.y, f0.z); gpk[1] = pkbf(f0.w, f1.y); gpk[2] = pkbf(f1.z, f1.w);
        gpk[3] = pkbf(f2.y, f2.z); gpk[4] = pkbf(f2.w, f3.y); gpk[5] = pkbf(f3.z, f3.w);
        gpk[6] = pkbf(f4v.y, f4v.z); gpk[7] = pkbf(f4v.w, f5.y); gpk[8] = pkbf(f5.z, f5.w);
    }

    while (row < B) {
        const int nrow = row + gstride;
        const bool pn = nrow < B;

        // ===== phase 1: sigma pieces + ActG + warp-private base (no block sync) =====
        float sg = sgpre + 1e-4f;
        sm[O_SIGP + par * 128 + tid] = sg;
        #pragma unroll
        for (int j = 0; j < 9; j++) smu[O_ACTG + agix(tid, j)] = gpk[j];

        {   // base = b0 + d . W0dir : two outputs per lane, warp-redundant
            const float2* b02 = (const float2*)(sm + O_B0);
            const float2* w0d2 = (const float2*)(sm + O_W0D);
            float2 acc = b02[lane];
            #pragma unroll
            for (int i = 0; i < DIRD; i++) {
                float di = __shfl_sync(0xffffffffu, dpre, i);
                float2 w = w0d2[i * 32 + lane];
                acc.x = fmaf(di, w.x, acc.x);
                acc.y = fmaf(di, w.y, acc.y);
            }
            ((float2*)(sm + O_BASEW + warp * 64))[lane] = acc;
        }

        // warp max of sg -> parity slot (consumed after the barrier below)
        {
            float m = sg;
            #pragma unroll
            for (int o = 16; o; o >>= 1) m = fmaxf(m, __shfl_xor_sync(0xffffffffu, m, o));
            if (lane == 0) sm[O_MAXP + par * 4 + warp] = m;
        }
        __syncwarp();   // ActG + base visible within warp

        // ---- prefetch stage 1: next row's x + d ----
        int2 xv0, xv1, xv2;
        if (pn) {
            const int2* xp2 = (const int2*)(x + ((size_t)nrow * BN + tid) * LVL);
            xv0 = __ldg(xp2); xv1 = __ldg(xp2 + 1); xv2 = __ldg(xp2 + 2);
            dpre = (lane < DIRD) ? __ldg(dvec + (size_t)nrow * DIRD + lane) : 0.0f;
        }

        const int r0 = warp * 32 + grp;
        const float* baseW = sm + O_BASEW + warp * 64;

        // ============ layer 0 -> A1 registers ============
        u32 A1[2][4][4];
        {
            u32 Ag[2][2][4];
            const u32* AG = smu + O_ACTG;
            #pragma unroll
            for (int mt = 0; mt < 2; mt++) {
                int rA = r0 + mt * 16, rB = rA + 8;
                #pragma unroll
                for (int k = 0; k < 2; k++) {
                    Ag[mt][k][0] = AG[agix(rA, k * 8 + tig)];
                    Ag[mt][k][1] = AG[agix(rB, k * 8 + tig)];
                    Ag[mt][k][2] = AG[agix(rA, k * 8 + 4 + tig)];
                    Ag[mt][k][3] = AG[agix(rB, k * 8 + 4 + tig)];
                }
            }
            const u32* WT = smu + O_W0GT;
            #pragma unroll
            for (int kg = 0; kg < 4; kg++) {
                float Ca[2][4], Cb[2][4];
                #pragma unroll
                for (int mt = 0; mt < 2; mt++) {
                    float v0 = baseW[(2 * kg) * 8 + 2 * tig];
                    float v1 = baseW[(2 * kg) * 8 + 2 * tig + 1];
                    Ca[mt][0] = v0; Ca[mt][1] = v1; Ca[mt][2] = v0; Ca[mt][3] = v1;
                    v0 = baseW[(2 * kg + 1) * 8 + 2 * tig];
                    v1 = baseW[(2 * kg + 1) * 8 + 2 * tig + 1];
                    Cb[mt][0] = v0; Cb[mt][1] = v1; Cb[mt][2] = v0; Cb[mt][3] = v1;
                }
                #pragma unroll
                for (int k = 0; k < 2; k++) {
                    u32 ba0 = WT[((2 * kg) * 8 + grp) * SW0G + k * 8 + tig];
                    u32 ba1 = WT[((2 * kg) * 8 + grp) * SW0G + k * 8 + 4 + tig];
                    u32 bb0 = WT[((2 * kg + 1) * 8 + grp) * SW0G + k * 8 + tig];
                    u32 bb1 = WT[((2 * kg + 1) * 8 + grp) * SW0G + k * 8 + 4 + tig];
                    #pragma unroll
                    for (int mt = 0; mt < 2; mt++) {
                        mma16(Ca[mt], Ag[mt][k], ba0, ba1);
                        mma16(Cb[mt], Ag[mt][k], bb0, bb1);
                    }
                }
                #pragma unroll
                for (int mt = 0; mt < 2; mt++) {
                    A1[mt][kg][0] = pkrelu(Ca[mt][0], Ca[mt][1]);
                    A1[mt][kg][1] = pkrelu(Ca[mt][2], Ca[mt][3]);
                    A1[mt][kg][2] = pkrelu(Cb[mt][0], Cb[mt][1]);
                    A1[mt][kg][3] = pkrelu(Cb[mt][2], Cb[mt][3]);
                }
            }
        }

        // ---- prefetch stage 2: dependent gathers -> packed form ----
        if (pn) {
            float4 f0 = __ldg(gw + xv0.x), f1 = __ldg(gw + xv0.y);
            float4 f2 = __ldg(gw + xv1.x), f3 = __ldg(gw + xv1.y);
            float4 f4v = __ldg(gw + xv2.x), f5 = __ldg(gw + xv2.y);
            sgpre = fminf(fmaxf(f0.x, 0.f), 1.f) * fminf(fmaxf(f1.x, 0.f), 1.f)
                  * fminf(fmaxf(f2.x, 0.f), 1.f) * fminf(fmaxf(f3.x, 0.f), 1.f)
                  * fminf(fmaxf(f4v.x, 0.f), 1.f) * fminf(fmaxf(f5.x, 0.f), 1.f);
            gpk[0] = pkbf(f0.y, f0.z); gpk[1] = pkbf(f0.w, f1.y); gpk[2] = pkbf(f1.z, f1.w);
            gpk[3] = pkbf(f2.y, f2.z); gpk[4] = pkbf(f2.w, f3.y); gpk[5] = pkbf(f3.z, f3.w);
            gpk[6] = pkbf(f4v.y, f4v.z); gpk[7] = pkbf(f4v.w, f5.y); gpk[8] = pkbf(f5.z, f5.w);
        }

        // ============ layer 1 -> A2 ============
        u32 A2[2][4][4];
        {
            const u32* WT = smu + O_W1T;
            #pragma unroll
            for (int kg = 0; kg < 4; kg++) {
                float Ca[2][4], Cb[2][4];
                #pragma unroll
                for (int mt = 0; mt < 2; mt++) {
                    float v0 = sm[O_B1 + (2 * kg) * 8 + 2 * tig];
                    float v1 = sm[O_B1 + (2 * kg) * 8 + 2 * tig + 1];
                    Ca[mt][0] = v0; Ca[mt][1] = v1; Ca[mt][2] = v0; Ca[mt][3] = v1;
                    v0 = sm[O_B1 + (2 * kg + 1) * 8 + 2 * tig];
                    v1 = sm[O_B1 + (2 * kg + 1) * 8 + 2 * tig + 1];
                    Cb[mt][0] = v0; Cb[mt][1] = v1; Cb[mt][2] = v0; Cb[mt][3] = v1;
                }
                #pragma unroll
                for (int k = 0; k < 4; k++) {
                    u32 ba0 = WT[((2 * kg) * 8 + grp) * SW1 + k * 8 + tig];
                    u32 ba1 = WT[((2 * kg) * 8 + grp) * SW1 + k * 8 + 4 + tig];
                    u32 bb0 = WT[((2 * kg + 1) * 8 + grp) * SW1 + k * 8 + tig];
                    u32 bb1 = WT[((2 * kg + 1) * 8 + grp) * SW1 + k * 8 + 4 + tig];
                    #pragma unroll
                    for (int mt = 0; mt < 2; mt++) {
                        mma16(Ca[mt], A1[mt][k], ba0, ba1);
                        mma16(Cb[mt], A1[mt][k], bb0, bb1);
                    }
                }
                #pragma unroll
                for (int mt = 0; mt < 2; mt++) {
                    A2[mt][kg][0] = pkrelu(Ca[mt][0], Ca[mt][1]);
                    A2[mt][kg][1] = pkrelu(Ca[mt][2], Ca[mt][3]);
                    A2[mt][kg][2] = pkrelu(Cb[mt][0], Cb[mt][1]);
                    A2[mt][kg][3] = pkrelu(Cb[mt][2], Cb[mt][3]);
                }
            }
        }

        // ============ layer 2 -> logits (warp-private COLB) ============
        {
            const u32* WT = smu + O_W2T;
            float bv0 = sm[O_B2 + 2 * tig];
            float bv1 = sm[O_B2 + 2 * tig + 1];
            float C0[4] = {bv0, bv1, bv0, bv1};
            float C1[4] = {bv0, bv1, bv0, bv1};
            #pragma unroll
            for (int k = 0; k < 4; k++) {
                u32 bb0 = WT[grp * SW2 + k * 8 + tig];
                u32 bb1 = WT[grp * SW2 + k * 8 + 4 + tig];
                mma16(C0, A2[0][k], bb0, bb1);
                mma16(C1, A2[1][k], bb0, bb1);
            }
            const int r1 = r0 + 16;
            if (2 * tig < 3) {
                sm[O_COLB + r0 * SCB + 2 * tig]        = C0[0];
                sm[O_COLB + (r0 + 8) * SCB + 2 * tig]  = C0[2];
                sm[O_COLB + r1 * SCB + 2 * tig]        = C1[0];
                sm[O_COLB + (r1 + 8) * SCB + 2 * tig]  = C1[2];
            }
            if (2 * tig + 1 < 3) {
                sm[O_COLB + r0 * SCB + 2 * tig + 1]       = C0[1];
                sm[O_COLB + (r0 + 8) * SCB + 2 * tig + 1] = C0[3];
                sm[O_COLB + r1 * SCB + 2 * tig + 1]       = C1[1];
                sm[O_COLB + (r1 + 8) * SCB + 2 * tig + 1] = C1[3];
            }
        }

        // ================= single block barrier =================
        __syncthreads();

        // ---- previous row's color output (parity^1 partials now complete) ----
        if (prevRow >= 0 && tid < 3) {
            const float* cp = sm + O_COLP + (par ^ 1) * 12;
            outColor[(size_t)prevRow * 3 + tid] = cp[tid] + cp[3 + tid] + cp[6 + tid] + cp[9 + tid];
        }

        // ---- this row's sigma + color partials ----
        float m = fmaxf(fmaxf(sm[O_MAXP + par * 4 + 0], sm[O_MAXP + par * 4 + 1]),
                        fmaxf(sm[O_MAXP + par * 4 + 2], sm[O_MAXP + par * 4 + 3]));
        float sigma = sg / m;
        outSigma[(size_t)row * BN + tid] = sigma;
        float tb = tid ? 1.0f - sm[O_SIGP + par * 128 + tid - 1] / m : 1.0f;
        float cw = tb * sigma;

        float l0 = sm[O_COLB + tid * SCB + 0];
        float l1 = sm[O_COLB + tid * SCB + 1];
        float l2 = sm[O_COLB + tid * SCB + 2];
        float c0 = 1.0f / (1.0f + expf(-l0));
        float c1 = 1.0f / (1.0f + expf(-l1));
        float c2 = 1.0f / (1.0f + expf(-l2));
        float rr = cw * c0, gg = cw * c1, bb = cw * c2;
        #pragma unroll
        for (int o = 16; o; o >>= 1) {
            rr += __shfl_xor_sync(0xffffffffu, rr, o);
            gg += __shfl_xor_sync(0xffffffffu, gg, o);
            bb += __shfl_xor_sync(0xffffffffu, bb, o);
        }
        if (lane == 0) {
            sm[O_COLP + par * 12 + warp * 3 + 0] = rr;
            sm[O_COLP + par * 12 + warp * 3 + 1] = gg;
            sm[O_COLP + par * 12 + warp * 3 + 2] = bb;
        }

        prevRow = row;
        row = nrow;
        par ^= 1;
    }

    // ---------- epilogue: flush last row's color ----------
    __syncthreads();
    if (prevRow >= 0 && tid < 3) {
        const float* cp = sm + O_COLP + (par ^ 1) * 12;
        outColor[(size_t)prevRow * 3 + tid] = cp[tid] + cp[3 + tid] + cp[6 + tid] + cp[9 + tid];
    }
}

extern "C" void kernel_launch(void* const* d_in, const int* in_sizes, int n_in,
                              void* d_out, int out_size)
{
    const int*    x  = (const int*)d_in[0];
    const float*  dv = (const float*)d_in[1];
    const float4* gw = (const float4*)d_in[2];
    const float*  W0 = (const float*)d_in[3];
    const float*  b0 = (const float*)d_in[4];
    const float*  W1 = (const float*)d_in[5];
    const float*  b1 = (const float*)d_in[6];
    const float*  W2 = (const float*)d_in[7];
    const float*  b2 = (const float*)d_in[8];

    const int B = in_sizes[0] / (BN * LVL);   // 16384
    float* outSigma = (float*)d_out;
    float* outColor = (float*)d_out + (size_t)B * BN;

    cudaFuncSetAttribute(surf_onesync,
                         cudaFuncAttributeMaxDynamicSharedMemorySize, SMEM_BYTES);

    int grid = B < 444 ? B : 444;   // 3 blocks/SM persistent
    surf_onesync<<<grid, 128, SMEM_BYTES>>>(x, dv, gw, W0, b0, W1, b1, W2, b2,
                                            outSigma, outColor, B);
}